// round 2
// baseline (speedup 1.0000x reference)
#include <cuda_runtime.h>
#include <cstdint>

#define T_DIM  4096
#define B_DIM  8192
#define CHUNKS 64
#define CL     64          // chunk length; CHUNKS*CL == T_DIM
#define WPC    (CL / 32)   // 32-bit words per chunk per sequence (=2)
#define GROUPS (B_DIM / 4) // thread-groups across batch (4 seqs per thread)

// Scratch: static device globals (allocation-free).
__device__ uint32_t g_bits[(T_DIM / 32) * B_DIM];     // 4 MB packed inputs
__device__ float    g_state[4][CHUNKS * B_DIM];       // 8 MB chunk states (n10,n11,na0,na1)

// ---------------------------------------------------------------------------
// Pass 1: per-chunk local recurrence from zero init; pack input bits.
// ---------------------------------------------------------------------------
__global__ void __launch_bounds__(256) lk_pass1(const float* __restrict__ in,
                                                const float* __restrict__ dptr) {
    const float d = dptr[0];
    const int c  = blockIdx.y;
    const int g  = blockIdx.x * blockDim.x + threadIdx.x; // 0..GROUPS-1
    const int b0 = g * 4;

    // prev = x[c*CL - 1] (zero for first chunk)
    bool prev[4];
    if (c == 0) {
        prev[0] = prev[1] = prev[2] = prev[3] = false;
    } else {
        float4 pv = *(const float4*)(in + (size_t)(c * CL - 1) * B_DIM + b0);
        prev[0] = pv.x != 0.f; prev[1] = pv.y != 0.f;
        prev[2] = pv.z != 0.f; prev[3] = pv.w != 0.f;
    }

    float n10[4] = {0.f, 0.f, 0.f, 0.f};
    float n11[4] = {0.f, 0.f, 0.f, 0.f};
    float na0[4] = {0.f, 0.f, 0.f, 0.f};
    float na1[4] = {0.f, 0.f, 0.f, 0.f};
    uint32_t bw[4][WPC];
#pragma unroll
    for (int s = 0; s < 4; ++s)
#pragma unroll
        for (int w = 0; w < WPC; ++w) bw[s][w] = 0u;

    const float4* p = (const float4*)(in + (size_t)(c * CL) * B_DIM + b0);

#pragma unroll
    for (int w = 0; w < WPC; ++w) {
#pragma unroll 8
        for (int i = 0; i < 32; ++i) {
            float4 x4 = *p;
            p += B_DIM / 4;
            float xs[4] = {x4.x, x4.y, x4.z, x4.w};
#pragma unroll
            for (int s = 0; s < 4; ++s) {
                bool cur = xs[s] != 0.f;
                bw[s][w] |= (uint32_t)cur << i;
                n10[s] = fmaf(d, n10[s], (cur && !prev[s]) ? d : 0.f);
                n11[s] = fmaf(d, n11[s], (cur &&  prev[s]) ? d : 0.f);
                na0[s] = fmaf(d, na0[s], (!prev[s]) ? d : 0.f);
                na1[s] = fmaf(d, na1[s], ( prev[s]) ? d : 0.f);
                prev[s] = cur;
            }
        }
    }

#pragma unroll
    for (int w = 0; w < WPC; ++w) {
        uint4 v = make_uint4(bw[0][w], bw[1][w], bw[2][w], bw[3][w]);
        *(uint4*)(g_bits + (size_t)(c * WPC + w) * B_DIM + b0) = v;
    }
    const int si = c * B_DIM + b0;
    *(float4*)(&g_state[0][si]) = make_float4(n10[0], n10[1], n10[2], n10[3]);
    *(float4*)(&g_state[1][si]) = make_float4(n11[0], n11[1], n11[2], n11[3]);
    *(float4*)(&g_state[2][si]) = make_float4(na0[0], na0[1], na0[2], na0[3]);
    *(float4*)(&g_state[3][si]) = make_float4(na1[0], na1[1], na1[2], na1[3]);
}

// ---------------------------------------------------------------------------
// Pass 2: exclusive scan over chunk states: A_c = local_c + d^CL * A_{c-1}.
// Rewrites g_state[comp][c][b] to the INITIAL state for chunk c.
// ---------------------------------------------------------------------------
__global__ void __launch_bounds__(256) lk_pass2(const float* __restrict__ dptr) {
    const float d = dptr[0];
    float dL = d;
#pragma unroll
    for (int i = 0; i < 6; ++i) dL *= dL;  // d^64 by repeated squaring

    const int comp = blockIdx.y;  // 0..3
    const int b    = blockIdx.x * blockDim.x + threadIdx.x;
    float* a = g_state[comp];

    float v[CHUNKS];
#pragma unroll
    for (int c = 0; c < CHUNKS; ++c) v[c] = a[(size_t)c * B_DIM + b];

    float acc = 0.f;
#pragma unroll
    for (int c = 0; c < CHUNKS; ++c) {
        float nv = fmaf(dL, acc, v[c]);
        v[c] = acc;   // exclusive prefix (init state for chunk c)
        acc = nv;
    }
#pragma unroll
    for (int c = 0; c < CHUNKS; ++c) a[(size_t)c * B_DIM + b] = v[c];
}

// ---------------------------------------------------------------------------
// Pass 3: replay recurrence from corrected init using packed bits; emit preds.
// ---------------------------------------------------------------------------
__global__ void __launch_bounds__(256) lk_pass3(const float* __restrict__ dptr,
                                                float* __restrict__ out) {
    const float d = dptr[0];
    const int c  = blockIdx.y;
    const int g  = blockIdx.x * blockDim.x + threadIdx.x;
    const int b0 = g * 4;
    const int si = c * B_DIM + b0;

    float4 v10 = *(const float4*)(&g_state[0][si]);
    float4 v11 = *(const float4*)(&g_state[1][si]);
    float4 va0 = *(const float4*)(&g_state[2][si]);
    float4 va1 = *(const float4*)(&g_state[3][si]);
    float n10[4] = {v10.x, v10.y, v10.z, v10.w};
    float n11[4] = {v11.x, v11.y, v11.z, v11.w};
    float na0[4] = {va0.x, va0.y, va0.z, va0.w};
    float na1[4] = {va1.x, va1.y, va1.z, va1.w};

    bool prev[4];
    if (c == 0) {
        prev[0] = prev[1] = prev[2] = prev[3] = false;
    } else {
        uint4 pw = *(const uint4*)(g_bits + (size_t)((c - 1) * WPC + (WPC - 1)) * B_DIM + b0);
        prev[0] = (pw.x >> 31) & 1u; prev[1] = (pw.y >> 31) & 1u;
        prev[2] = (pw.z >> 31) & 1u; prev[3] = (pw.w >> 31) & 1u;
    }

    uint32_t bw[4][WPC];
#pragma unroll
    for (int w = 0; w < WPC; ++w) {
        uint4 t = *(const uint4*)(g_bits + (size_t)(c * WPC + w) * B_DIM + b0);
        bw[0][w] = t.x; bw[1][w] = t.y; bw[2][w] = t.z; bw[3][w] = t.w;
    }

    float4* po = (float4*)(out + (size_t)(c * CL) * B_DIM + b0);

#pragma unroll
    for (int w = 0; w < WPC; ++w) {
#pragma unroll 8
        for (int i = 0; i < 32; ++i) {
            float ov[4];
#pragma unroll
            for (int s = 0; s < 4; ++s) {
                bool cur = (bw[s][w] >> i) & 1u;
                n10[s] = fmaf(d, n10[s], (cur && !prev[s]) ? d : 0.f);
                n11[s] = fmaf(d, n11[s], (cur &&  prev[s]) ? d : 0.f);
                na0[s] = fmaf(d, na0[s], (!prev[s]) ? d : 0.f);
                na1[s] = fmaf(d, na1[s], ( prev[s]) ? d : 0.f);
                float num = cur ? (n11[s] + 1.f) : (n10[s] + 1.f);
                float den = cur ? (na1[s] + 2.f) : (na0[s] + 2.f);
                ov[s] = __fdividef(num, den);
                prev[s] = cur;
            }
            *po = make_float4(ov[0], ov[1], ov[2], ov[3]);
            po += B_DIM / 4;
        }
    }
}

// ---------------------------------------------------------------------------
extern "C" void kernel_launch(void* const* d_in, const int* in_sizes, int n_in,
                              void* d_out, int out_size) {
    const float* in   = (const float*)d_in[0];
    const float* dptr = (const float*)d_in[1];
    if (n_in >= 2 && in_sizes[0] == 1) {  // defensive: metadata order swap
        in   = (const float*)d_in[1];
        dptr = (const float*)d_in[0];
    }
    float* out = (float*)d_out;

    dim3 blk(256);
    dim3 grid13(GROUPS / 256, CHUNKS);   // (8, 64)
    dim3 grid2(B_DIM / 256, 4);          // (32, 4)

    lk_pass1<<<grid13, blk>>>(in, dptr);
    lk_pass2<<<grid2, blk>>>(dptr);
    lk_pass3<<<grid13, blk>>>(dptr, out);
}

// round 3
// speedup vs baseline: 1.0684x; 1.0684x over previous
#include <cuda_runtime.h>
#include <cstdint>

#define T_DIM  4096
#define B_DIM  8192
#define CHUNKS 128
#define CL     32          // chunk length; CHUNKS*CL == T_DIM
#define GROUPS (B_DIM / 4) // thread-groups across batch (4 seqs per thread)

// Scratch: static device globals (allocation-free).
__device__ uint32_t g_bits[CHUNKS * B_DIM];          // 4 MB packed inputs (1 word/chunk/seq)
__device__ float    g_state[3][CHUNKS * B_DIM];      // 12 MB chunk states (n1tot, n11, na1)

// ---------------------------------------------------------------------------
// Pass 1: per-chunk local recurrence from zero init; pack input bits.
// Uses x ∈ {0,1} as float directly — pure FMA-pipe accumulator updates.
// ---------------------------------------------------------------------------
__global__ void __launch_bounds__(256) lk_pass1(const float* __restrict__ in,
                                                const float* __restrict__ dptr) {
    const float d = dptr[0];
    const int c  = blockIdx.y;
    const int g  = blockIdx.x * blockDim.x + threadIdx.x; // 0..GROUPS-1
    const int b0 = g * 4;

    // prev_d = d * x[c*CL - 1]  (zero for first chunk)
    float prev_d[4] = {0.f, 0.f, 0.f, 0.f};
    if (c != 0) {
        float4 pv = *(const float4*)(in + (size_t)(c * CL - 1) * B_DIM + b0);
        prev_d[0] = pv.x * d; prev_d[1] = pv.y * d;
        prev_d[2] = pv.z * d; prev_d[3] = pv.w * d;
    }

    float n1t[4] = {0.f, 0.f, 0.f, 0.f};   // n10 + n11
    float n11[4] = {0.f, 0.f, 0.f, 0.f};
    float na1[4] = {0.f, 0.f, 0.f, 0.f};
    uint32_t bw[4] = {0u, 0u, 0u, 0u};

    const float4* __restrict__ p = (const float4*)(in + (size_t)(c * CL) * B_DIM + b0);

#pragma unroll
    for (int i = 0; i < CL; ++i) {
        float4 x4 = p[(size_t)i * (B_DIM / 4)];
        float xs[4] = {x4.x, x4.y, x4.z, x4.w};
#pragma unroll
        for (int s = 0; s < 4; ++s) {
            float curf = xs[s];                    // 0.0f or 1.0f
            if (curf != 0.f) bw[s] |= (1u << i);
            float cur_d = curf * d;
            n11[s] = fmaf(d, n11[s], curf * prev_d[s]);
            na1[s] = fmaf(d, na1[s], prev_d[s]);
            n1t[s] = fmaf(d, n1t[s], cur_d);
            prev_d[s] = cur_d;
        }
    }

    *(uint4*)(g_bits + (size_t)c * B_DIM + b0) = make_uint4(bw[0], bw[1], bw[2], bw[3]);
    const size_t si = (size_t)c * B_DIM + b0;
    *(float4*)(&g_state[0][si]) = make_float4(n1t[0], n1t[1], n1t[2], n1t[3]);
    *(float4*)(&g_state[1][si]) = make_float4(n11[0], n11[1], n11[2], n11[3]);
    *(float4*)(&g_state[2][si]) = make_float4(na1[0], na1[1], na1[2], na1[3]);
}

// ---------------------------------------------------------------------------
// Pass 2: exclusive scan over chunk states: carry_c = local_c + d^CL * carry_{c-1}.
// Rewrites g_state[comp][c][b] to the INITIAL (carry-in) state for chunk c.
// Streamed in batches of 32 to keep registers bounded with MLP=32.
// ---------------------------------------------------------------------------
__global__ void __launch_bounds__(256) lk_pass2(const float* __restrict__ dptr) {
    const float d = dptr[0];
    float dL = d;
#pragma unroll
    for (int i = 0; i < 5; ++i) dL *= dL;  // d^32 by repeated squaring

    const int comp = blockIdx.y;  // 0..2
    const int b    = blockIdx.x * blockDim.x + threadIdx.x;
    float* a = g_state[comp];

    float acc = 0.f;
#pragma unroll
    for (int batch = 0; batch < CHUNKS / 32; ++batch) {
        float v[32];
#pragma unroll
        for (int j = 0; j < 32; ++j)
            v[j] = a[(size_t)(batch * 32 + j) * B_DIM + b];
#pragma unroll
        for (int j = 0; j < 32; ++j) {
            float nv = fmaf(dL, acc, v[j]);
            v[j] = acc;           // exclusive prefix
            acc = nv;
        }
#pragma unroll
        for (int j = 0; j < 32; ++j)
            a[(size_t)(batch * 32 + j) * B_DIM + b] = v[j];
    }
}

// ---------------------------------------------------------------------------
// Pass 3: replay recurrence from corrected init using packed bits; emit preds.
// na0 reconstructed from the deterministic all-count S_t; n10 = n1tot - n11.
// ---------------------------------------------------------------------------
__global__ void __launch_bounds__(256) lk_pass3(const float* __restrict__ dptr,
                                                float* __restrict__ out) {
    const float d = dptr[0];
    const int c  = blockIdx.y;
    const int g  = blockIdx.x * blockDim.x + threadIdx.x;
    const int b0 = g * 4;
    const size_t si = (size_t)c * B_DIM + b0;

    float4 v1t = *(const float4*)(&g_state[0][si]);
    float4 v11 = *(const float4*)(&g_state[1][si]);
    float4 va1 = *(const float4*)(&g_state[2][si]);
    float n1t[4] = {v1t.x, v1t.y, v1t.z, v1t.w};
    float n11[4] = {v11.x, v11.y, v11.z, v11.w};
    float na1[4] = {va1.x, va1.y, va1.z, va1.w};

    // Deterministic total-count carry-in: S = A_{cs-1} = d * (1 - d^{cs}) / (1 - d)
    float dL = d;
#pragma unroll
    for (int i = 0; i < 5; ++i) dL *= dL;   // d^CL
    float dcs = 1.f, base = dL;
    int e = c;
    while (e) { if (e & 1) dcs *= base; base *= base; e >>= 1; }
    float S = (c == 0) ? 0.f : d * (1.f - dcs) / (1.f - d);

    // prev_d from last bit of previous chunk
    float prev_d[4] = {0.f, 0.f, 0.f, 0.f};
    if (c != 0) {
        uint4 pw = *(const uint4*)(g_bits + (size_t)(c - 1) * B_DIM + b0);
        prev_d[0] = (pw.x >> 31) ? d : 0.f;
        prev_d[1] = (pw.y >> 31) ? d : 0.f;
        prev_d[2] = (pw.z >> 31) ? d : 0.f;
        prev_d[3] = (pw.w >> 31) ? d : 0.f;
    }

    uint4 bwv = *(const uint4*)(g_bits + (size_t)c * B_DIM + b0);
    uint32_t bw[4] = {bwv.x, bwv.y, bwv.z, bwv.w};

    float4* __restrict__ po = (float4*)(out + (size_t)(c * CL) * B_DIM + b0);

#pragma unroll
    for (int i = 0; i < CL; ++i) {
        S = fmaf(d, S, d);  // shared across the 4 sequences
        float ov[4];
#pragma unroll
        for (int s = 0; s < 4; ++s) {
            bool cur = (bw[s] >> i) & 1u;
            float cur_d = cur ? d : 0.f;
            n11[s] = fmaf(d, n11[s], cur ? prev_d[s] : 0.f);
            na1[s] = fmaf(d, na1[s], prev_d[s]);
            n1t[s] = fmaf(d, n1t[s], cur_d);
            prev_d[s] = cur_d;
            float num = (cur ? n11[s] : n1t[s] - n11[s]) + 1.f;
            float den = (cur ? na1[s] : S - na1[s]) + 2.f;
            ov[s] = __fdividef(num, den);
        }
        po[(size_t)i * (B_DIM / 4)] = make_float4(ov[0], ov[1], ov[2], ov[3]);
    }
}

// ---------------------------------------------------------------------------
extern "C" void kernel_launch(void* const* d_in, const int* in_sizes, int n_in,
                              void* d_out, int out_size) {
    const float* in   = (const float*)d_in[0];
    const float* dptr = (const float*)d_in[1];
    if (n_in >= 2 && in_sizes[0] == 1) {  // defensive: metadata order swap
        in   = (const float*)d_in[1];
        dptr = (const float*)d_in[0];
    }
    float* out = (float*)d_out;

    dim3 blk(256);
    dim3 grid13(GROUPS / 256, CHUNKS);   // (8, 128)
    dim3 grid2(B_DIM / 256, 3);          // (32, 3)

    lk_pass1<<<grid13, blk>>>(in, dptr);
    lk_pass2<<<grid2, blk>>>(dptr);
    lk_pass3<<<grid13, blk>>>(dptr, out);
}

// round 4
// speedup vs baseline: 1.0765x; 1.0075x over previous
#include <cuda_runtime.h>
#include <cstdint>

#define T_DIM  4096
#define B_DIM  8192
#define CHUNKS 128
#define CL     32          // chunk length; CHUNKS*CL == T_DIM
#define SPT    2           // sequences per thread
#define GROUPS (B_DIM / SPT)

// Scratch: static device globals (allocation-free). 16 MB total -> fits in L2.
__device__ uint32_t g_bits[CHUNKS * B_DIM];          // 4 MB packed inputs
__device__ float    g_state[3][CHUNKS * B_DIM];      // 12 MB chunk states (n1tot, n11, na1)

// ---------------------------------------------------------------------------
// Pass 1: per-chunk local recurrence from zero init; pack input bits.
// 2 seqs/thread, explicit 8-deep streaming load batches for MLP.
// ---------------------------------------------------------------------------
__global__ void __launch_bounds__(256, 6) lk_pass1(const float* __restrict__ in,
                                                   const float* __restrict__ dptr) {
    const float d = dptr[0];
    const int c  = blockIdx.y;
    const int t  = blockIdx.x * blockDim.x + threadIdx.x; // 0..GROUPS-1
    const int b0 = t * SPT;

    // prev_d = d * x[c*CL - 1]  (zero for first chunk)
    float prev_d[SPT] = {0.f, 0.f};
    if (c != 0) {
        float2 pv = __ldcs((const float2*)(in + (size_t)(c * CL - 1) * B_DIM + b0));
        prev_d[0] = pv.x * d; prev_d[1] = pv.y * d;
    }

    float n1t[SPT] = {0.f, 0.f};   // n10 + n11
    float n11[SPT] = {0.f, 0.f};
    float na1[SPT] = {0.f, 0.f};
    uint32_t bw[SPT] = {0u, 0u};

    const float2* __restrict__ p = (const float2*)(in + (size_t)(c * CL) * B_DIM + b0);

#pragma unroll
    for (int ii = 0; ii < CL; ii += 8) {
        float2 x[8];
#pragma unroll
        for (int j = 0; j < 8; ++j)
            x[j] = __ldcs(p + (size_t)(ii + j) * (B_DIM / 2));
#pragma unroll
        for (int j = 0; j < 8; ++j) {
            float xs[SPT] = {x[j].x, x[j].y};
#pragma unroll
            for (int s = 0; s < SPT; ++s) {
                float curf = xs[s];                     // 0.0f or 1.0f
                bw[s] |= (curf != 0.f) ? (1u << (ii + j)) : 0u;
                float cur_d = curf * d;
                n11[s] = fmaf(d, n11[s], curf * prev_d[s]);
                na1[s] = fmaf(d, na1[s], prev_d[s]);
                n1t[s] = fmaf(d, n1t[s], cur_d);
                prev_d[s] = cur_d;
            }
        }
    }

    *(uint2*)(g_bits + (size_t)c * B_DIM + b0) = make_uint2(bw[0], bw[1]);
    const size_t si = (size_t)c * B_DIM + b0;
    *(float2*)(&g_state[0][si]) = make_float2(n1t[0], n1t[1]);
    *(float2*)(&g_state[1][si]) = make_float2(n11[0], n11[1]);
    *(float2*)(&g_state[2][si]) = make_float2(na1[0], na1[1]);
}

// ---------------------------------------------------------------------------
// Pass 2: exclusive scan over chunk states: carry_c = local_c + d^CL * carry_{c-1}.
// Rewrites g_state[comp][c][b] to the INITIAL (carry-in) state for chunk c.
// ---------------------------------------------------------------------------
__global__ void __launch_bounds__(256) lk_pass2(const float* __restrict__ dptr) {
    const float d = dptr[0];
    float dL = d;
#pragma unroll
    for (int i = 0; i < 5; ++i) dL *= dL;  // d^32 by repeated squaring

    const int comp = blockIdx.y;  // 0..2
    const int b    = blockIdx.x * blockDim.x + threadIdx.x;
    float* a = g_state[comp];

    float acc = 0.f;
#pragma unroll
    for (int batch = 0; batch < CHUNKS / 32; ++batch) {
        float v[32];
#pragma unroll
        for (int j = 0; j < 32; ++j)
            v[j] = a[(size_t)(batch * 32 + j) * B_DIM + b];
#pragma unroll
        for (int j = 0; j < 32; ++j) {
            float nv = fmaf(dL, acc, v[j]);
            v[j] = acc;           // exclusive prefix
            acc = nv;
        }
#pragma unroll
        for (int j = 0; j < 32; ++j)
            a[(size_t)(batch * 32 + j) * B_DIM + b] = v[j];
    }
}

// ---------------------------------------------------------------------------
// Pass 3: replay recurrence from corrected init using packed bits; emit preds.
// na0 reconstructed from the deterministic all-count S_t; n10 = n1tot - n11.
// ---------------------------------------------------------------------------
__global__ void __launch_bounds__(256, 6) lk_pass3(const float* __restrict__ dptr,
                                                   float* __restrict__ out) {
    const float d = dptr[0];
    const int c  = blockIdx.y;
    const int t  = blockIdx.x * blockDim.x + threadIdx.x;
    const int b0 = t * SPT;
    const size_t si = (size_t)c * B_DIM + b0;

    float2 v1t = *(const float2*)(&g_state[0][si]);
    float2 v11 = *(const float2*)(&g_state[1][si]);
    float2 va1 = *(const float2*)(&g_state[2][si]);
    float n1t[SPT] = {v1t.x, v1t.y};
    float n11[SPT] = {v11.x, v11.y};
    float na1[SPT] = {va1.x, va1.y};

    // Deterministic total-count carry-in: S = d * (1 - d^{c*CL}) / (1 - d)
    float dL = d;
#pragma unroll
    for (int i = 0; i < 5; ++i) dL *= dL;   // d^CL
    float dcs = 1.f, base = dL;
    int e = c;
    while (e) { if (e & 1) dcs *= base; base *= base; e >>= 1; }
    float S = (c == 0) ? 0.f : d * (1.f - dcs) / (1.f - d);

    // prev_d from last bit of previous chunk
    float prev_d[SPT] = {0.f, 0.f};
    if (c != 0) {
        uint2 pw = *(const uint2*)(g_bits + (size_t)(c - 1) * B_DIM + b0);
        prev_d[0] = (pw.x >> 31) ? d : 0.f;
        prev_d[1] = (pw.y >> 31) ? d : 0.f;
    }

    uint2 bwv = *(const uint2*)(g_bits + (size_t)c * B_DIM + b0);
    uint32_t bw[SPT] = {bwv.x, bwv.y};

    float2* __restrict__ po = (float2*)(out + (size_t)(c * CL) * B_DIM + b0);

#pragma unroll
    for (int i = 0; i < CL; ++i) {
        S = fmaf(d, S, d);  // shared across the sequences
        float ov[SPT];
#pragma unroll
        for (int s = 0; s < SPT; ++s) {
            bool cur = (bw[s] >> i) & 1u;
            float cur_d = cur ? d : 0.f;
            n11[s] = fmaf(d, n11[s], cur ? prev_d[s] : 0.f);
            na1[s] = fmaf(d, na1[s], prev_d[s]);
            n1t[s] = fmaf(d, n1t[s], cur_d);
            prev_d[s] = cur_d;
            float num = (cur ? n11[s] : n1t[s] - n11[s]) + 1.f;
            float den = (cur ? na1[s] : S - na1[s]) + 2.f;
            ov[s] = __fdividef(num, den);
        }
        __stcs(po + (size_t)i * (B_DIM / 2), make_float2(ov[0], ov[1]));
    }
}

// ---------------------------------------------------------------------------
extern "C" void kernel_launch(void* const* d_in, const int* in_sizes, int n_in,
                              void* d_out, int out_size) {
    const float* in   = (const float*)d_in[0];
    const float* dptr = (const float*)d_in[1];
    if (n_in >= 2 && in_sizes[0] == 1) {  // defensive: metadata order swap
        in   = (const float*)d_in[1];
        dptr = (const float*)d_in[0];
    }
    float* out = (float*)d_out;

    dim3 blk(256);
    dim3 grid13(GROUPS / 256, CHUNKS);   // (16, 128)
    dim3 grid2(B_DIM / 256, 3);          // (32, 3)

    lk_pass1<<<grid13, blk>>>(in, dptr);
    lk_pass2<<<grid2, blk>>>(dptr);
    lk_pass3<<<grid13, blk>>>(dptr, out);
}